// round 1
// baseline (speedup 1.0000x reference)
#include <cuda_runtime.h>

#define N_TRAJ 512
#define P_DIM  256
#define NW     8      // warps per block

__global__ __launch_bounds__(256, 3) void loa_bfgs_kernel(
    const float* __restrict__ grad,
    const float* __restrict__ gradm1,
    const float* __restrict__ dm1,
    const float* __restrict__ M,       // (N, P, P), row-major
    const float* __restrict__ Wfs,     // (1,6)
    const float* __restrict__ Wo1,     // (6,3)
    const float* __restrict__ Wo2,     // (12,6)
    const float* __restrict__ Wo3,     // (3,12)
    const float* __restrict__ Wl1,     // (12,6)
    const float* __restrict__ Wl2,     // (24,12)
    const float* __restrict__ Wl3,     // (1,24)
    float* __restrict__ dout)          // (N, P)
{
    const int n    = blockIdx.x;
    const int tid  = threadIdx.x;
    const int lane = tid & 31;
    const int warp = tid >> 5;

    __shared__ float s_g[P_DIM];      // grad[n]
    __shared__ float s_dg[P_DIM];     // grad - gradm1
    __shared__ float s_dm1[P_DIM];
    __shared__ float s_QNDG[P_DIM];   // M @ dg
    __shared__ float s_Mg[P_DIM];     // M @ grad
    __shared__ float s_w[516];        // all weights packed
    __shared__ float s_red[NW][4];
    __shared__ float s_scal[8];       // [0..2]=of mean, [4..7]=denom,sdg,og,sg

    // ---- stage per-trajectory vectors ----
    {
        float gv = grad[n * P_DIM + tid];
        float gm = gradm1[n * P_DIM + tid];
        s_g[tid]   = gv;
        s_dg[tid]  = gv - gm;
        s_dm1[tid] = dm1[n * P_DIM + tid];
    }
    // ---- stage weights: [Wfs 0:6 | Wo1 6:24 | Wo2 24:96 | Wo3 96:132 | Wl1 132:204 | Wl2 204:492 | Wl3 492:516]
    for (int i = tid; i < 516; i += 256) {
        float w;
        if      (i < 6)   w = Wfs[i];
        else if (i < 24)  w = Wo1[i - 6];
        else if (i < 96)  w = Wo2[i - 24];
        else if (i < 132) w = Wo3[i - 96];
        else if (i < 204) w = Wl1[i - 132];
        else if (i < 492) w = Wl2[i - 204];
        else              w = Wl3[i - 492];
        s_w[i] = w;
    }
    __syncthreads();

    // ---- phase 1: two fused mat-vecs, warp-per-row, float4 coalesced ----
    {
        const float4* g4  = reinterpret_cast<const float4*>(s_g);
        const float4* dg4 = reinterpret_cast<const float4*>(s_dg);
        // each lane owns fixed q-slices: [4*lane .. 4*lane+3] and [128+4*lane ..]
        const float4 gv0 = g4[lane],  gv1 = g4[32 + lane];
        const float4 dv0 = dg4[lane], dv1 = dg4[32 + lane];
        const float4* Mb = reinterpret_cast<const float4*>(M + (size_t)n * P_DIM * P_DIM);

        #pragma unroll 4
        for (int r = 0; r < 32; ++r) {
            const int p = warp * 32 + r;
            const float4* row = Mb + (size_t)p * (P_DIM / 4);
            const float4 a0 = row[lane];
            const float4 a1 = row[32 + lane];

            float s1 = a0.x * dv0.x + a0.y * dv0.y + a0.z * dv0.z + a0.w * dv0.w
                     + a1.x * dv1.x + a1.y * dv1.y + a1.z * dv1.z + a1.w * dv1.w;
            float s2 = a0.x * gv0.x + a0.y * gv0.y + a0.z * gv0.z + a0.w * gv0.w
                     + a1.x * gv1.x + a1.y * gv1.y + a1.z * gv1.z + a1.w * gv1.w;

            #pragma unroll
            for (int o = 16; o; o >>= 1) {
                s1 += __shfl_xor_sync(0xffffffffu, s1, o);
                s2 += __shfl_xor_sync(0xffffffffu, s2, o);
            }
            if (lane == 0) { s_QNDG[p] = s1; s_Mg[p] = s2; }
        }
    }
    __syncthreads();

    // ---- phase 2: outer MLP per p, then mean over P ----
    const float x0 = s_QNDG[tid];     // QNDG
    const float x1 = s_dm1[tid];      // dm1
    const float x2 = -s_Mg[tid];      // Bg = -GAMMA * M@grad, GAMMA=1

    const float* wo1 = s_w + 6;
    const float* wo2 = s_w + 24;
    const float* wo3 = s_w + 96;

    float h1[6];
    #pragma unroll
    for (int i = 0; i < 6; ++i) {
        float a = wo1[i*3+0]*x0 + wo1[i*3+1]*x1 + wo1[i*3+2]*x2;
        h1[i] = fmaxf(a, 0.0f);
    }
    float h2[12];
    #pragma unroll
    for (int i = 0; i < 12; ++i) {
        float a = 0.0f;
        #pragma unroll
        for (int j = 0; j < 6; ++j) a += wo2[i*6+j] * h1[j];
        h2[i] = fmaxf(a, 0.0f);
    }
    float of0 = 0.f, of1 = 0.f, of2 = 0.f;
    #pragma unroll
    for (int j = 0; j < 12; ++j) {
        of0 += wo3[0*12+j] * h2[j];
        of1 += wo3[1*12+j] * h2[j];
        of2 += wo3[2*12+j] * h2[j];
    }
    #pragma unroll
    for (int o = 16; o; o >>= 1) {
        of0 += __shfl_xor_sync(0xffffffffu, of0, o);
        of1 += __shfl_xor_sync(0xffffffffu, of1, o);
        of2 += __shfl_xor_sync(0xffffffffu, of2, o);
    }
    if (lane == 0) { s_red[warp][0] = of0; s_red[warp][1] = of1; s_red[warp][2] = of2; }
    __syncthreads();
    if (tid < 3) {
        float a = 0.0f;
        #pragma unroll
        for (int w = 0; w < NW; ++w) a += s_red[w][tid];
        s_scal[tid] = a * (1.0f / P_DIM);
    }
    __syncthreads();

    // ---- phase 3: full-skip + inner MLP -> out[p] ----
    const float f0 = s_scal[0], f1 = s_scal[1], f2 = s_scal[2];
    float x6[6] = {x0, x1, x2, f0, f1, f2};

    float fullskip = s_w[0]*x0 + s_w[1]*x1 + s_w[2]*x2
                   + s_w[3]*f0 + s_w[4]*f1 + s_w[5]*f2;

    const float* wl1 = s_w + 132;
    const float* wl2 = s_w + 204;
    const float* wl3 = s_w + 492;

    float l1[12];
    #pragma unroll
    for (int i = 0; i < 12; ++i) {
        float a = 0.0f;
        #pragma unroll
        for (int j = 0; j < 6; ++j) a += wl1[i*6+j] * x6[j];
        l1[i] = fmaxf(a, 0.0f);
    }
    float l2[24];
    #pragma unroll
    for (int i = 0; i < 24; ++i) {
        float a = 0.0f;
        #pragma unroll
        for (int j = 0; j < 12; ++j) a += wl2[i*12+j] * l1[j];
        l2[i] = fmaxf(a, 0.0f);
    }
    float out_p = fullskip;
    #pragma unroll
    for (int j = 0; j < 24; ++j) out_p += wl3[j] * l2[j];

    // ---- phase 4: BFGS scalars (4 dot products over P) ----
    const float sec = x1 - x0;        // secant = dm1 - QNDG
    const float dgk = s_dg[tid];      // DGK
    const float gv  = s_g[tid];

    float r0 = out_p * dgk;           // denom
    float r1 = sec   * dgk;           // secant . DGK
    float r2 = out_p * gv;            // out . grad
    float r3 = sec   * gv;            // secant . grad
    #pragma unroll
    for (int o = 16; o; o >>= 1) {
        r0 += __shfl_xor_sync(0xffffffffu, r0, o);
        r1 += __shfl_xor_sync(0xffffffffu, r1, o);
        r2 += __shfl_xor_sync(0xffffffffu, r2, o);
        r3 += __shfl_xor_sync(0xffffffffu, r3, o);
    }
    if (lane == 0) {
        s_red[warp][0] = r0; s_red[warp][1] = r1;
        s_red[warp][2] = r2; s_red[warp][3] = r3;
    }
    __syncthreads();
    if (tid < 4) {
        float a = 0.0f;
        #pragma unroll
        for (int w = 0; w < NW; ++w) a += s_red[w][tid];
        s_scal[4 + tid] = a;
    }
    __syncthreads();

    // ---- phase 5: d[p] = -(M@grad)[p] - upd@grad[p] ----
    const float denom = s_scal[4];
    const float sdg   = s_scal[5];
    const float og    = s_scal[6];
    const float sg    = s_scal[7];
    const float norm  = 1.0f / denom;
    const float coef  = sdg * norm;

    // upd @ v, v = -grad:
    // d[p] = -Mg[p] - norm*(sec[p]*og + out[p]*sg - coef*out[p]*og)
    float dval = -s_Mg[tid] - norm * (sec * og + out_p * sg - coef * out_p * og);
    dout[n * P_DIM + tid] = dval;
}

extern "C" void kernel_launch(void* const* d_in, const int* in_sizes, int n_in,
                              void* d_out, int out_size) {
    const float* grad   = (const float*)d_in[0];
    const float* gradm1 = (const float*)d_in[1];
    const float* dm1    = (const float*)d_in[2];
    const float* M      = (const float*)d_in[3];
    const float* Wfs    = (const float*)d_in[4];
    const float* Wo1    = (const float*)d_in[5];
    const float* Wo2    = (const float*)d_in[6];
    const float* Wo3    = (const float*)d_in[7];
    const float* Wl1    = (const float*)d_in[8];
    const float* Wl2    = (const float*)d_in[9];
    const float* Wl3    = (const float*)d_in[10];
    float* out = (float*)d_out;

    loa_bfgs_kernel<<<N_TRAJ, 256>>>(grad, gradm1, dm1, M,
                                     Wfs, Wo1, Wo2, Wo3, Wl1, Wl2, Wl3, out);
}

// round 2
// speedup vs baseline: 1.0909x; 1.0909x over previous
#include <cuda_runtime.h>

#define N_TRAJ 512
#define P_DIM  256
#define CHUNKS 8               // CTAs per trajectory in matvec kernel
#define ROWS_PER_CTA (P_DIM / CHUNKS)   // 32
#define NW     8               // warps per block (kernel B)

// scratch: QNDG = M@(grad-gradm1), Mg = M@grad
__device__ float g_scrQ[N_TRAJ * P_DIM];
__device__ float g_scrM[N_TRAJ * P_DIM];

// ---------------------------------------------------------------------------
// Kernel A: dual mat-vec, streaming M once. 4096 CTAs x 256 threads.
// Each warp handles 4 rows; lane owns fixed q-slices [4*lane..] and [128+4*lane..].
// ---------------------------------------------------------------------------
__global__ __launch_bounds__(256, 4) void matvec_kernel(
    const float* __restrict__ grad,
    const float* __restrict__ gradm1,
    const float* __restrict__ M)
{
    const int b     = blockIdx.x;
    const int n     = b >> 3;          // trajectory
    const int chunk = b & 7;           // 32-row chunk
    const int lane  = threadIdx.x & 31;
    const int warp  = threadIdx.x >> 5;

    // broadcast vectors straight from global (L2-resident, 512KB total)
    const float4* gg = reinterpret_cast<const float4*>(grad   + n * P_DIM);
    const float4* gm = reinterpret_cast<const float4*>(gradm1 + n * P_DIM);
    const float4 gv0 = gg[lane], gv1 = gg[32 + lane];
    const float4 m0  = gm[lane], m1  = gm[32 + lane];
    const float4 dv0 = make_float4(gv0.x - m0.x, gv0.y - m0.y, gv0.z - m0.z, gv0.w - m0.w);
    const float4 dv1 = make_float4(gv1.x - m1.x, gv1.y - m1.y, gv1.z - m1.z, gv1.w - m1.w);

    const int row0 = chunk * ROWS_PER_CTA + warp * 4;   // 4 rows per warp
    const float4* Mb = reinterpret_cast<const float4*>(M + (size_t)n * P_DIM * P_DIM);

    #pragma unroll
    for (int r = 0; r < 4; ++r) {
        const int p = row0 + r;
        const float4* row = Mb + (size_t)p * (P_DIM / 4);
        const float4 a0 = row[lane];
        const float4 a1 = row[32 + lane];

        float s1 = a0.x * dv0.x + a0.y * dv0.y + a0.z * dv0.z + a0.w * dv0.w
                 + a1.x * dv1.x + a1.y * dv1.y + a1.z * dv1.z + a1.w * dv1.w;
        float s2 = a0.x * gv0.x + a0.y * gv0.y + a0.z * gv0.z + a0.w * gv0.w
                 + a1.x * gv1.x + a1.y * gv1.y + a1.z * gv1.z + a1.w * gv1.w;

        #pragma unroll
        for (int o = 16; o; o >>= 1) {
            s1 += __shfl_xor_sync(0xffffffffu, s1, o);
            s2 += __shfl_xor_sync(0xffffffffu, s2, o);
        }
        if (lane == 0) {
            g_scrQ[n * P_DIM + p] = s1;
            g_scrM[n * P_DIM + p] = s2;
        }
    }
}

// ---------------------------------------------------------------------------
// Kernel B: MLPs + BFGS scalars + final d. 512 CTAs x 256 threads. Tiny.
// ---------------------------------------------------------------------------
__global__ __launch_bounds__(256) void epilogue_kernel(
    const float* __restrict__ grad,
    const float* __restrict__ gradm1,
    const float* __restrict__ dm1,
    const float* __restrict__ Wfs,     // (1,6)
    const float* __restrict__ Wo1,     // (6,3)
    const float* __restrict__ Wo2,     // (12,6)
    const float* __restrict__ Wo3,     // (3,12)
    const float* __restrict__ Wl1,     // (12,6)
    const float* __restrict__ Wl2,     // (24,12)
    const float* __restrict__ Wl3,     // (1,24)
    float* __restrict__ dout)          // (N, P)
{
    const int n    = blockIdx.x;
    const int tid  = threadIdx.x;
    const int lane = tid & 31;
    const int warp = tid >> 5;

    __shared__ float s_w[516];
    __shared__ float s_red[NW][4];
    __shared__ float s_scal[8];

    // per-thread values
    const float gv  = grad[n * P_DIM + tid];
    const float dgk = gv - gradm1[n * P_DIM + tid];
    const float x0  = g_scrQ[n * P_DIM + tid];   // QNDG
    const float x1  = dm1[n * P_DIM + tid];
    const float Mg  = g_scrM[n * P_DIM + tid];
    const float x2  = -Mg;                       // Bg

    // weights: [Wfs 0:6 | Wo1 6:24 | Wo2 24:96 | Wo3 96:132 | Wl1 132:204 | Wl2 204:492 | Wl3 492:516]
    for (int i = tid; i < 516; i += 256) {
        float w;
        if      (i < 6)   w = Wfs[i];
        else if (i < 24)  w = Wo1[i - 6];
        else if (i < 96)  w = Wo2[i - 24];
        else if (i < 132) w = Wo3[i - 96];
        else if (i < 204) w = Wl1[i - 132];
        else if (i < 492) w = Wl2[i - 204];
        else              w = Wl3[i - 492];
        s_w[i] = w;
    }
    __syncthreads();

    // outer MLP
    const float* wo1 = s_w + 6;
    const float* wo2 = s_w + 24;
    const float* wo3 = s_w + 96;

    float h1[6];
    #pragma unroll
    for (int i = 0; i < 6; ++i) {
        float a = wo1[i*3+0]*x0 + wo1[i*3+1]*x1 + wo1[i*3+2]*x2;
        h1[i] = fmaxf(a, 0.0f);
    }
    float h2[12];
    #pragma unroll
    for (int i = 0; i < 12; ++i) {
        float a = 0.0f;
        #pragma unroll
        for (int j = 0; j < 6; ++j) a += wo2[i*6+j] * h1[j];
        h2[i] = fmaxf(a, 0.0f);
    }
    float of0 = 0.f, of1 = 0.f, of2 = 0.f;
    #pragma unroll
    for (int j = 0; j < 12; ++j) {
        of0 += wo3[0*12+j] * h2[j];
        of1 += wo3[1*12+j] * h2[j];
        of2 += wo3[2*12+j] * h2[j];
    }
    #pragma unroll
    for (int o = 16; o; o >>= 1) {
        of0 += __shfl_xor_sync(0xffffffffu, of0, o);
        of1 += __shfl_xor_sync(0xffffffffu, of1, o);
        of2 += __shfl_xor_sync(0xffffffffu, of2, o);
    }
    if (lane == 0) { s_red[warp][0] = of0; s_red[warp][1] = of1; s_red[warp][2] = of2; }
    __syncthreads();
    if (tid < 3) {
        float a = 0.0f;
        #pragma unroll
        for (int w = 0; w < NW; ++w) a += s_red[w][tid];
        s_scal[tid] = a * (1.0f / P_DIM);
    }
    __syncthreads();

    // full-skip + inner MLP
    const float f0 = s_scal[0], f1 = s_scal[1], f2 = s_scal[2];
    float x6[6] = {x0, x1, x2, f0, f1, f2};

    float fullskip = s_w[0]*x0 + s_w[1]*x1 + s_w[2]*x2
                   + s_w[3]*f0 + s_w[4]*f1 + s_w[5]*f2;

    const float* wl1 = s_w + 132;
    const float* wl2 = s_w + 204;
    const float* wl3 = s_w + 492;

    float l1[12];
    #pragma unroll
    for (int i = 0; i < 12; ++i) {
        float a = 0.0f;
        #pragma unroll
        for (int j = 0; j < 6; ++j) a += wl1[i*6+j] * x6[j];
        l1[i] = fmaxf(a, 0.0f);
    }
    float l2[24];
    #pragma unroll
    for (int i = 0; i < 24; ++i) {
        float a = 0.0f;
        #pragma unroll
        for (int j = 0; j < 12; ++j) a += wl2[i*12+j] * l1[j];
        l2[i] = fmaxf(a, 0.0f);
    }
    float out_p = fullskip;
    #pragma unroll
    for (int j = 0; j < 24; ++j) out_p += wl3[j] * l2[j];

    // BFGS scalars
    const float sec = x1 - x0;

    float r0 = out_p * dgk;           // denom
    float r1 = sec   * dgk;           // secant . DGK
    float r2 = out_p * gv;            // out . grad
    float r3 = sec   * gv;            // secant . grad
    #pragma unroll
    for (int o = 16; o; o >>= 1) {
        r0 += __shfl_xor_sync(0xffffffffu, r0, o);
        r1 += __shfl_xor_sync(0xffffffffu, r1, o);
        r2 += __shfl_xor_sync(0xffffffffu, r2, o);
        r3 += __shfl_xor_sync(0xffffffffu, r3, o);
    }
    if (lane == 0) {
        s_red[warp][0] = r0; s_red[warp][1] = r1;
        s_red[warp][2] = r2; s_red[warp][3] = r3;
    }
    __syncthreads();
    if (tid < 4) {
        float a = 0.0f;
        #pragma unroll
        for (int w = 0; w < NW; ++w) a += s_red[w][tid];
        s_scal[4 + tid] = a;
    }
    __syncthreads();

    const float denom = s_scal[4];
    const float sdg   = s_scal[5];
    const float og    = s_scal[6];
    const float sg    = s_scal[7];
    const float norm  = 1.0f / denom;
    const float coef  = sdg * norm;

    // d[p] = -Mg[p] - norm*(sec[p]*og + out[p]*sg - coef*out[p]*og)
    float dval = -Mg - norm * (sec * og + out_p * sg - coef * out_p * og);
    dout[n * P_DIM + tid] = dval;
}

extern "C" void kernel_launch(void* const* d_in, const int* in_sizes, int n_in,
                              void* d_out, int out_size) {
    const float* grad   = (const float*)d_in[0];
    const float* gradm1 = (const float*)d_in[1];
    const float* dm1    = (const float*)d_in[2];
    const float* M      = (const float*)d_in[3];
    const float* Wfs    = (const float*)d_in[4];
    const float* Wo1    = (const float*)d_in[5];
    const float* Wo2    = (const float*)d_in[6];
    const float* Wo3    = (const float*)d_in[7];
    const float* Wl1    = (const float*)d_in[8];
    const float* Wl2    = (const float*)d_in[9];
    const float* Wl3    = (const float*)d_in[10];
    float* out = (float*)d_out;

    matvec_kernel<<<N_TRAJ * CHUNKS, 256>>>(grad, gradm1, M);
    epilogue_kernel<<<N_TRAJ, 256>>>(grad, gradm1, dm1,
                                     Wfs, Wo1, Wo2, Wo3, Wl1, Wl2, Wl3, out);
}